// round 16
// baseline (speedup 1.0000x reference)
#include <cuda_runtime.h>
#include <math.h>
#include <stdint.h>

// Shapes (fixed for this problem)
#define kB 4
#define kH 12
#define kS 2048
#define kD 64
#define BSv 64
#define Lv 32
#define NSTEPS 4
#define BH (kB*kH)

typedef unsigned long long ull;

// ---------------- device scratch (module-load allocated) ----------------
__device__ float g_lp[(size_t)BH*BSv*Lv*Lv];      // [bh][j][l][k]
__device__ float g_rp[(size_t)BH*Lv*BSv*BSv];     // [bh][k][j][i]
__device__ float g_KR[(size_t)BH*Lv*BSv*kD];      // [bh][k][j][v]  (reused as Y at the end)
__device__ float g_LQ[(size_t)BH*BSv*Lv*kD];      // [bh][j][kk][v]
__device__ float g_r2[BH*Lv*BSv];                 // [bh][k][j]
__device__ float g_l2[BH*BSv*Lv];                 // [bh][j][k]
__device__ float g_leftF[(size_t)BH*BSv*Lv*Lv];   // final left [bh][j][l][k]
__device__ float g_eta[kH*2*NSTEPS];              // softplus(step_size)
__device__ float g_asc[kH];                       // softplus(attention_scale)/sqrt(D)

__device__ __forceinline__ float softplusf(float x) {
    return x > 20.f ? x : log1pf(expf(x));
}

__device__ __forceinline__ float rsum16(float v) {
    v += __shfl_xor_sync(0xffffffffu, v, 8);
    v += __shfl_xor_sync(0xffffffffu, v, 4);
    v += __shfl_xor_sync(0xffffffffu, v, 2);
    v += __shfl_xor_sync(0xffffffffu, v, 1);
    return v;
}

// ---- packed f32x2 helpers (FFMA2) ----
__device__ __forceinline__ ull pdup(float x) {
    ull r; asm("mov.b64 %0, {%1, %1};" : "=l"(r) : "f"(x)); return r;
}
__device__ __forceinline__ float2 up2(ull v) {
    float2 r; asm("mov.b64 {%0, %1}, %2;" : "=f"(r.x), "=f"(r.y) : "l"(v)); return r;
}
__device__ __forceinline__ void fma2(ull &d, ull a, ull b) {
    asm("fma.rn.f32x2 %0, %1, %2, %0;" : "+l"(d) : "l"(a), "l"(b));
}

__device__ __forceinline__ void cp_async16(uint32_t smem_addr, const void* gptr) {
    asm volatile("cp.async.cg.shared.global [%0], [%1], 16;"
                 :: "r"(smem_addr), "l"(gptr) : "memory");
}
__device__ __forceinline__ void cp_async_commit() {
    asm volatile("cp.async.commit_group;" ::: "memory");
}
__device__ __forceinline__ void cp_async_wait0() {
    asm volatile("cp.async.wait_group 0;" ::: "memory");
}

// ---------------- prep: eta, asc ----------------
__global__ void __launch_bounds__(128) prep_kernel(const float* __restrict__ ascale,
                                                   const float* __restrict__ ssize) {
    int i = threadIdx.x;
    if (i < kH*2*NSTEPS) g_eta[i] = softplusf(ssize[i]);
    if (i < kH) g_asc[i] = softplusf(ascale[i]) * 0.125f;   // 1/sqrt(64)
}

// ---------------- step-0 KR: right0 == 1/64 -> KR0 = colmean of K ----------------
__global__ void __launch_bounds__(256) init_kr_kernel(const float* __restrict__ key) {
    int bh = blockIdx.x / Lv;
    int k  = blockIdx.x % Lv;
    const float* Kt = key + ((size_t)bh*kS + (size_t)k*BSv) * kD;
    __shared__ float s_m[kD];
    int tid = threadIdx.x;
    if (tid < kD) {
        float s = 0.f;
        #pragma unroll 8
        for (int i = 0; i < BSv; i++) s += Kt[(size_t)i*kD + tid];
        s_m[tid] = s * (1.0f/64.0f);
    }
    __syncthreads();
    float* KRo = g_KR + ((size_t)(bh*Lv + k) * BSv) * kD;
    #pragma unroll
    for (int it = 0; it < (BSv*kD)/256; it++) {
        int idx = tid + it*256;
        KRo[idx] = s_m[idx & 63];
    }
}

// ---------------- left step: per (bh, j), fused, FFMA2 ----------------
// Transposed arrays use XOR swizzle: phys(l, v) = v*32 + (l ^ (((v>>1)&15)<<1))
// regs were 52 -> 4 CTAs (reg-bound; smem allows 7). __launch_bounds__(256,6)
// targets <=42 regs -> 6 CTAs = 48 warps/SM, same lever that won in right_step.
template<bool INIT, bool LAST>
__global__ void __launch_bounds__(256, 6) left_step_kernel(const float* __restrict__ query, int s) {
    __shared__ float s_left[Lv*Lv];
    __shared__ float s_qT[kD*Lv];
    __shared__ float s_krT[kD*Lv];
    __shared__ float s_q[Lv*kD];
    __shared__ float s_r2c[Lv];

    int bh = blockIdx.x / BSv;
    int j  = blockIdx.x % BSv;
    int h  = bh % kH;
    int tid = threadIdx.x;
    int tx = tid & 15;        // k-tile index
    int ty = tid >> 4;        // l-tile index
    int l0 = ty*2, k0 = tx*2;

    const size_t lp_base = ((size_t)(bh*BSv + j)) * (Lv*Lv);

    // prefetch lp early (hide latency behind fill + GEMM)
    float2 lpre[2];
    if (!INIT) {
        #pragma unroll
        for (int r = 0; r < 2; r++)
            lpre[r] = *(const float2*)&g_lp[lp_base + (size_t)(l0+r)*Lv + k0];
    }
    // hoisted strided r2 gather (previously issued right before the barrier -> exposed)
    float r2v = 0.f;
    if (!INIT && tid < Lv) r2v = g_r2[(bh*Lv + tid)*BSv + j];

    // load Q (scaled) and KR; build row-major s_q and swizzled transposes
    float qsc = g_asc[h];
    const float* KRb = g_KR + (size_t)bh*Lv*BSv*kD;
    #pragma unroll
    for (int it = 0; it < 2; it++) {
        int idx = tid + it*256;            // 0..511 float4s
        int row = idx >> 4;                // l  0..31
        int m   = idx & 15;
        int vq  = m*4;
        size_t goff = ((size_t)bh*kS + (size_t)row*BSv + j)*kD + vq;
        float4 q4 = *(const float4*)&query[goff];
        q4.x *= qsc; q4.y *= qsc; q4.z *= qsc; q4.w *= qsc;
        *(float4*)&s_q[row*kD + vq] = q4;
        float4 kr4 = *(const float4*)&KRb[((size_t)row*BSv + j)*kD + vq];
        float qv[4] = {q4.x,q4.y,q4.z,q4.w};
        float kv[4] = {kr4.x,kr4.y,kr4.z,kr4.w};
        #pragma unroll
        for (int t = 0; t < 4; t++) {
            int v  = vq + t;
            int sl = row ^ (((v>>1)&15)<<1);
            s_qT [v*Lv + sl] = qv[t];
            s_krT[v*Lv + sl] = kv[t];
        }
    }
    if (!INIT && tid < Lv) s_r2c[tid] = r2v;
    __syncthreads();

    // t2l[l][k] in registers: rows l0,l0+1 ; k-pair k0,k0+1 (packed f32x2)
    ull accA = 0ull, accB = 0ull;
    #pragma unroll
    for (int v = 0; v < kD; v++) {
        int X = ((v>>1)&15)<<1;
        float2 a = *(const float2*)&s_qT[v*Lv + (l0^X)];
        ull b = *(const ull*)&s_krT[v*Lv + (k0^X)];
        fma2(accA, pdup(a.x), b);
        fma2(accB, pdup(a.y), b);
    }
    float2 t2l0 = up2(accA), t2l1 = up2(accB);

    // fused: normalize lp row, dl, project, update; store left (pre-update)
    float eta = g_eta[h*(2*NSTEPS) + s];
    float r2c0 = INIT ? 0.015625f : s_r2c[k0];
    float r2c1 = INIT ? 0.015625f : s_r2c[k0+1];
    #pragma unroll
    for (int r = 0; r < 2; r++) {
        int lr = l0 + r;
        float2 lp2 = INIT ? make_float2(0.17677669529663687f, 0.17677669529663687f)
                          : lpre[r];
        float ss = rsum16(lp2.x*lp2.x + lp2.y*lp2.y);
        float n  = sqrtf(ss);
        float sc   = n > 0.f ? 1.0f/n : 1.0f;
        float invn = n > 0.f ? 1.0f/n : 0.0f;
        float ls0 = lp2.x*sc, ls1 = lp2.y*sc;
        float le0 = ls0*ls0,  le1 = ls1*ls1;
        *(float2*)&s_left[lr*Lv + k0] = make_float2(le0, le1);
        float t0 = (r==0) ? t2l0.x : t2l1.x;
        float t1 = (r==0) ? t2l0.y : t2l1.y;
        float dl0 = (r2c0*le0 - t0) * 2.f * ls0;
        float dl1 = (r2c1*le1 - t1) * 2.f * ls1;
        float dot = rsum16(ls0*dl0 + ls1*dl1);
        dl0 = (dl0 - ls0*dot) * invn;
        dl1 = (dl1 - ls1*dot) * invn;
        float np0 = lp2.x - eta*dl0;
        float np1 = lp2.y - eta*dl1;
        if (!LAST) {
            *(float2*)&g_lp[lp_base + (size_t)lr*Lv + k0] = make_float2(np0, np1);
        } else {
            float ss2 = rsum16(np0*np0 + np1*np1);
            float n2  = sqrtf(ss2);
            float sc2 = n2 > 0.f ? 1.0f/n2 : 1.0f;
            float f0 = np0*sc2, f1 = np1*sc2;
            *(float2*)&g_leftF[lp_base + (size_t)lr*Lv + k0] = make_float2(f0*f0, f1*f1);
        }
    }
    __syncthreads();

    // l2[k] = sum_l left^2
    if (tid < Lv) {
        float acc = 0.f;
        #pragma unroll
        for (int l = 0; l < Lv; l++) { float vv = s_left[l*Lv + tid]; acc += vv*vv; }
        g_l2[(size_t)(bh*BSv + j)*Lv + tid] = acc;
    }

    // LQ[kk][v] = sum_l left[l][kk]*q[l][v] : kk pair ty*2, v0=tx*4, FFMA2
    {
        int kk0 = ty*2, v0 = tx*4;
        ull a0p0=0ull, a0p1=0ull, a1p0=0ull, a1p1=0ull;
        #pragma unroll
        for (int l = 0; l < Lv; l++) {
            float2 a = *(const float2*)&s_left[l*Lv + kk0];
            ulonglong2 b = *(const ulonglong2*)&s_q[l*kD + v0];
            ull ad0 = pdup(a.x), ad1 = pdup(a.y);
            fma2(a0p0, ad0, b.x); fma2(a0p1, ad0, b.y);
            fma2(a1p0, ad1, b.x); fma2(a1p1, ad1, b.y);
        }
        float* LQo = g_LQ + ((size_t)(bh*BSv + j)) * Lv * kD;
        float2 r00 = up2(a0p0), r01 = up2(a0p1), r10 = up2(a1p0), r11 = up2(a1p1);
        *(float4*)&LQo[(size_t)kk0*kD + v0]     = make_float4(r00.x,r00.y,r01.x,r01.y);
        *(float4*)&LQo[(size_t)(kk0+1)*kD + v0] = make_float4(r10.x,r10.y,r11.x,r11.y);
    }
}

// ---------------- right step: per (bh, k), fused, FFMA2 ----------------
// Transposed arrays use XOR swizzle: phys(i, v) = v*64 + (i ^ (((v>>2)&7)<<2))
// smem 33KB (rp staging removed), __launch_bounds__(256,5) -> regs=48, 5 CTAs/SM.
#define SMEM_RT_FLOATS (4096*2 + 64)

template<bool INIT, int MODE>  // MODE 0 = update rp + next KR/r2 ; 1 = last step: Y from V
__global__ void __launch_bounds__(256, 5) right_step_kernel(const float* __restrict__ key,
                                                            const float* __restrict__ val,
                                                            int s) {
    extern __shared__ float sm[];
    float* s_KT  = sm;            // swizzled transposed K [v][i']; after GEMM1: swizzled rightT [i][j']
    float* s_LQT = sm + 4096;     // swizzled transposed LQ [v][j']; after GEMM1: row-major Km (cp.async)
    float* s_l2  = sm + 8192;     // 64

    int bh = blockIdx.x / Lv;
    int k  = blockIdx.x % Lv;
    int h  = bh % kH;
    int tid = threadIdx.x;
    int tx = tid & 15;
    int ty = tid >> 4;
    int j0 = ty*4, i0 = tx*4;

    const size_t rp_base = ((size_t)(bh*Lv + k)) * (BSv*BSv);
    const float* Kt  = key + ((size_t)bh*kS + (size_t)k*BSv) * kD;
    const float* Vt  = val + ((size_t)bh*kS + (size_t)k*BSv) * kD;
    const float* LQb = g_LQ + (size_t)bh*BSv*Lv*kD + (size_t)k*kD;

    // load K and LQ, transposed+swizzled
    #pragma unroll
    for (int it = 0; it < 4; it++) {
        int idx = tid + it*256;        // 0..1023 float4s
        int row = idx >> 4;            // i or j: 0..63
        int m   = idx & 15;
        int vq  = m*4;
        int sr  = row ^ ((m & 7) << 2);
        float4 k4 = *(const float4*)&Kt[(size_t)row*kD + vq];
        float4 l4 = *(const float4*)&LQb[(size_t)row*(Lv*kD) + vq];
        s_KT [(vq+0)*BSv + sr] = k4.x; s_KT [(vq+1)*BSv + sr] = k4.y;
        s_KT [(vq+2)*BSv + sr] = k4.z; s_KT [(vq+3)*BSv + sr] = k4.w;
        s_LQT[(vq+0)*BSv + sr] = l4.x; s_LQT[(vq+1)*BSv + sr] = l4.y;
        s_LQT[(vq+2)*BSv + sr] = l4.z; s_LQT[(vq+3)*BSv + sr] = l4.w;
    }
    if (tid < BSv) s_l2[tid] = g_l2[(size_t)(bh*BSv + tid)*Lv + k];
    __syncthreads();

    // GEMM1: t2r[j][i] = sum_v LQ[j][v]*K[i][v]  (registers, 4x4 tiles, packed f32x2)
    ull acc[4][2] = {};
    #pragma unroll
    for (int v = 0; v < kD; v++) {
        int xo = ((v>>2)&7)<<2;
        float4 a4 = *(const float4*)&s_LQT[v*BSv + (j0^xo)];
        ulonglong2 b2 = *(const ulonglong2*)&s_KT[v*BSv + (i0^xo)];
        ull a0 = pdup(a4.x), a1 = pdup(a4.y), a2 = pdup(a4.z), a3 = pdup(a4.w);
        fma2(acc[0][0], a0, b2.x); fma2(acc[0][1], a0, b2.y);
        fma2(acc[1][0], a1, b2.x); fma2(acc[1][1], a1, b2.y);
        fma2(acc[2][0], a2, b2.x); fma2(acc[2][1], a2, b2.y);
        fma2(acc[3][0], a3, b2.x); fma2(acc[3][1], a3, b2.y);
    }
    __syncthreads();   // everyone done reading s_KT / s_LQT

    // Km (K for MODE0, V for MODE1) -> s_LQT region, overlapped with dr phase
    {
        uint32_t sdst = (uint32_t)__cvta_generic_to_shared(s_LQT);
        const float4* Gp = (const float4*)(MODE == 0 ? Kt : Vt);
        #pragma unroll
        for (int it = 0; it < 4; it++) {
            int idx = tid + it*256;          // 0..1023 float4s
            cp_async16(sdst + (uint32_t)idx*16, Gp + idx);
        }
        cp_async_commit();
    }

    // fused dr: normalize rp row (gmem, in-loop — measured equal to smem staging),
    // grad, project, update, renormalize; rightT -> s_KT
    float eta = g_eta[h*(2*NSTEPS) + NSTEPS + s];
    int sxo = (tx & 7) << 2;   // ((i0+c)>>2 & 7)<<2, constant over c
    #pragma unroll
    for (int r = 0; r < 4; r++) {
        int jr = j0 + r;
        float4 rp4 = INIT ? make_float4(0.125f, 0.125f, 0.125f, 0.125f)
                          : *(const float4*)&g_rp[rp_base + (size_t)jr*BSv + i0];
        float ss = rsum16(rp4.x*rp4.x + rp4.y*rp4.y + rp4.z*rp4.z + rp4.w*rp4.w);
        float n  = sqrtf(ss);
        float sc   = n > 0.f ? 1.0f/n : 1.0f;
        float invn = n > 0.f ? 1.0f/n : 0.0f;
        float rs0 = rp4.x*sc, rs1 = rp4.y*sc, rs2 = rp4.z*sc, rs3 = rp4.w*sc;
        float l2v = s_l2[jr];
        float2 t01 = up2(acc[r][0]);
        float2 t23 = up2(acc[r][1]);
        float dr0 = (l2v*rs0*rs0 - t01.x) * 2.f * rs0;
        float dr1 = (l2v*rs1*rs1 - t01.y) * 2.f * rs1;
        float dr2 = (l2v*rs2*rs2 - t23.x) * 2.f * rs2;
        float dr3 = (l2v*rs3*rs3 - t23.y) * 2.f * rs3;
        float dot = rsum16(rs0*dr0 + rs1*dr1 + rs2*dr2 + rs3*dr3);
        dr0 = (dr0 - rs0*dot) * invn;
        dr1 = (dr1 - rs1*dot) * invn;
        dr2 = (dr2 - rs2*dot) * invn;
        dr3 = (dr3 - rs3*dot) * invn;
        float np0 = rp4.x - eta*dr0;
        float np1 = rp4.y - eta*dr1;
        float np2 = rp4.z - eta*dr2;
        float np3 = rp4.w - eta*dr3;
        if (MODE == 0) {
            *(float4*)&g_rp[rp_base + (size_t)jr*BSv + i0] = make_float4(np0,np1,np2,np3);
        }
        float ss2 = rsum16(np0*np0 + np1*np1 + np2*np2 + np3*np3);
        float n2  = sqrtf(ss2);
        float sc2 = n2 > 0.f ? 1.0f/n2 : 1.0f;
        float rn0 = np0*sc2, rn1 = np1*sc2, rn2 = np2*sc2, rn3 = np3*sc2;
        float rt0 = rn0*rn0, rt1 = rn1*rn1, rt2 = rn2*rn2, rt3 = rn3*rn3;
        // rightT[i][j'] into s_KT region (swizzled on i)
        int sj = jr ^ sxo;
        s_KT[(i0+0)*BSv + sj] = rt0;
        s_KT[(i0+1)*BSv + sj] = rt1;
        s_KT[(i0+2)*BSv + sj] = rt2;
        s_KT[(i0+3)*BSv + sj] = rt3;
        if (MODE == 0) {
            float r2s = rsum16(rt0*rt0 + rt1*rt1 + rt2*rt2 + rt3*rt3);
            if (tx == 0) g_r2[(bh*Lv + k)*BSv + jr] = r2s;
        }
    }
    cp_async_wait0();   // Km complete
    __syncthreads();

    // GEMM2: OUT[j][v] = sum_i rightT[i][j] * Km[i][v]  -> g_KR (next KR, or Y)
    float* outp = g_KR + ((size_t)(bh*Lv + k) * BSv) * kD;
    {
        int v0 = tx*4;
        ull acc2[4][2] = {};
        #pragma unroll
        for (int i = 0; i < BSv; i++) {
            int xo = ((i>>2)&7)<<2;
            float4 a4 = *(const float4*)&s_KT[i*BSv + (j0^xo)];
            ulonglong2 b2 = *(const ulonglong2*)&s_LQT[i*kD + v0];
            ull a0 = pdup(a4.x), a1 = pdup(a4.y), a2 = pdup(a4.z), a3 = pdup(a4.w);
            fma2(acc2[0][0], a0, b2.x); fma2(acc2[0][1], a0, b2.y);
            fma2(acc2[1][0], a1, b2.x); fma2(acc2[1][1], a1, b2.y);
            fma2(acc2[2][0], a2, b2.x); fma2(acc2[2][1], a2, b2.y);
            fma2(acc2[3][0], a3, b2.x); fma2(acc2[3][1], a3, b2.y);
        }
        #pragma unroll
        for (int r = 0; r < 4; r++) {
            float2 o01 = up2(acc2[r][0]);
            float2 o23 = up2(acc2[r][1]);
            *(float4*)&outp[(size_t)(j0+r)*kD + v0] = make_float4(o01.x,o01.y,o23.x,o23.y);
        }
    }
}

// ---------------- final Z = left @ Y, scatter to output ----------------
__global__ void __launch_bounds__(256) zout_kernel(float* __restrict__ out) {
    __shared__ float s_left[Lv*Lv];
    __shared__ float s_y[Lv*kD];
    int bh = blockIdx.x / BSv;
    int j  = blockIdx.x % BSv;
    int tid = threadIdx.x;
    size_t lbase = ((size_t)(bh*BSv + j)) * (Lv*Lv);
    #pragma unroll
    for (int it = 0; it < 4; it++) {
        int idx = tid + it*256;
        s_left[idx] = g_leftF[lbase + idx];
    }
    const float* Yb = g_KR + (size_t)bh*Lv*BSv*kD + (size_t)j*kD;
    #pragma unroll
    for (int it = 0; it < 8; it++) {
        int idx = tid + it*256;
        int kk = idx >> 6, v = idx & 63;
        s_y[kk*kD + v] = Yb[(size_t)kk*(BSv*kD) + v];
    }
    __syncthreads();
    int tx = tid & 15, ty = tid >> 4;
    int l00 = ty*2, v0 = tx*4;
    ull a0p0=0ull, a0p1=0ull, a1p0=0ull, a1p1=0ull;
    #pragma unroll
    for (int kk = 0; kk < Lv; kk++) {
        float a0 = s_left[l00*Lv + kk];
        float a1 = s_left[(l00+1)*Lv + kk];
        ulonglong2 b = *(const ulonglong2*)&s_y[kk*kD + v0];
        ull ad0 = pdup(a0), ad1 = pdup(a1);
        fma2(a0p0, ad0, b.x); fma2(a0p1, ad0, b.y);
        fma2(a1p0, ad1, b.x); fma2(a1p1, ad1, b.y);
    }
    float2 r00 = up2(a0p0), r01 = up2(a0p1), r10 = up2(a1p0), r11 = up2(a1p1);
    *(float4*)&out[((size_t)bh*kS + (size_t)l00*BSv + j)*kD + v0] =
        make_float4(r00.x,r00.y,r01.x,r01.y);
    *(float4*)&out[((size_t)bh*kS + (size_t)(l00+1)*BSv + j)*kD + v0] =
        make_float4(r10.x,r10.y,r11.x,r11.y);
}

// ---------------- launch ----------------
extern "C" void kernel_launch(void* const* d_in, const int* in_sizes, int n_in,
                              void* d_out, int out_size) {
    (void)in_sizes; (void)n_in; (void)out_size;
    const float* q      = (const float*)d_in[0];
    const float* key    = (const float*)d_in[1];
    const float* val    = (const float*)d_in[2];
    const float* ascale = (const float*)d_in[3];
    const float* ssz    = (const float*)d_in[4];
    float* out = (float*)d_out;

    const size_t SMEM_R = (size_t)SMEM_RT_FLOATS * sizeof(float);
    cudaFuncSetAttribute(right_step_kernel<true,0>,  cudaFuncAttributeMaxDynamicSharedMemorySize, (int)SMEM_R);
    cudaFuncSetAttribute(right_step_kernel<false,0>, cudaFuncAttributeMaxDynamicSharedMemorySize, (int)SMEM_R);
    cudaFuncSetAttribute(right_step_kernel<false,1>, cudaFuncAttributeMaxDynamicSharedMemorySize, (int)SMEM_R);

    prep_kernel<<<1, 128>>>(ascale, ssz);
    init_kr_kernel<<<BH*Lv, 256>>>(key);

    // s = 0 (INIT: lp/rp are exact constants)
    left_step_kernel<true,false><<<BH*BSv, 256>>>(q, 0);
    right_step_kernel<true,0><<<BH*Lv, 256, SMEM_R>>>(key, val, 0);
    // s = 1..2
    for (int s = 1; s < NSTEPS-1; s++) {
        left_step_kernel<false,false><<<BH*BSv, 256>>>(q, s);
        right_step_kernel<false,0><<<BH*Lv, 256, SMEM_R>>>(key, val, s);
    }
    // s = 3 (LAST: left -> leftF, right -> Y from V)
    left_step_kernel<false,true><<<BH*BSv, 256>>>(q, NSTEPS-1);
    right_step_kernel<false,1><<<BH*Lv, 256, SMEM_R>>>(key, val, NSTEPS-1);

    zout_kernel<<<BH*BSv, 256>>>(out);
}

// round 17
// speedup vs baseline: 1.0353x; 1.0353x over previous
#include <cuda_runtime.h>
#include <math.h>
#include <stdint.h>

// Shapes (fixed for this problem)
#define kB 4
#define kH 12
#define kS 2048
#define kD 64
#define BSv 64
#define Lv 32
#define NSTEPS 4
#define BH (kB*kH)

typedef unsigned long long ull;

// ---------------- device scratch (module-load allocated) ----------------
__device__ float g_lp[(size_t)BH*BSv*Lv*Lv];      // [bh][j][l][k]
__device__ float g_rp[(size_t)BH*Lv*BSv*BSv];     // [bh][k][j][i]
__device__ float g_KR[(size_t)BH*Lv*BSv*kD];      // [bh][k][j][v]  (reused as Y at the end)
__device__ float g_LQ[(size_t)BH*BSv*Lv*kD];      // [bh][j][kk][v]
__device__ float g_r2[BH*Lv*BSv];                 // [bh][k][j]
__device__ float g_l2[BH*BSv*Lv];                 // [bh][j][k]
__device__ float g_leftF[(size_t)BH*BSv*Lv*Lv];   // final left [bh][j][l][k]
__device__ float g_eta[kH*2*NSTEPS];              // softplus(step_size)
__device__ float g_asc[kH];                       // softplus(attention_scale)/sqrt(D)

__device__ __forceinline__ float softplusf(float x) {
    return x > 20.f ? x : log1pf(expf(x));
}

__device__ __forceinline__ float rsum16(float v) {
    v += __shfl_xor_sync(0xffffffffu, v, 8);
    v += __shfl_xor_sync(0xffffffffu, v, 4);
    v += __shfl_xor_sync(0xffffffffu, v, 2);
    v += __shfl_xor_sync(0xffffffffu, v, 1);
    return v;
}

// ---- packed f32x2 helpers (FFMA2) ----
__device__ __forceinline__ ull pdup(float x) {
    ull r; asm("mov.b64 %0, {%1, %1};" : "=l"(r) : "f"(x)); return r;
}
__device__ __forceinline__ float2 up2(ull v) {
    float2 r; asm("mov.b64 {%0, %1}, %2;" : "=f"(r.x), "=f"(r.y) : "l"(v)); return r;
}
__device__ __forceinline__ void fma2(ull &d, ull a, ull b) {
    asm("fma.rn.f32x2 %0, %1, %2, %0;" : "+l"(d) : "l"(a), "l"(b));
}

__device__ __forceinline__ void cp_async16(uint32_t smem_addr, const void* gptr) {
    asm volatile("cp.async.cg.shared.global [%0], [%1], 16;"
                 :: "r"(smem_addr), "l"(gptr) : "memory");
}
__device__ __forceinline__ void cp_async_commit() {
    asm volatile("cp.async.commit_group;" ::: "memory");
}
__device__ __forceinline__ void cp_async_wait0() {
    asm volatile("cp.async.wait_group 0;" ::: "memory");
}

// ---------------- prep: eta, asc ----------------
__global__ void __launch_bounds__(128) prep_kernel(const float* __restrict__ ascale,
                                                   const float* __restrict__ ssize) {
    int i = threadIdx.x;
    if (i < kH*2*NSTEPS) g_eta[i] = softplusf(ssize[i]);
    if (i < kH) g_asc[i] = softplusf(ascale[i]) * 0.125f;   // 1/sqrt(64)
}

// ---------------- step-0 KR: right0 == 1/64 -> KR0 = colmean of K ----------------
__global__ void __launch_bounds__(256) init_kr_kernel(const float* __restrict__ key) {
    int bh = blockIdx.x / Lv;
    int k  = blockIdx.x % Lv;
    const float* Kt = key + ((size_t)bh*kS + (size_t)k*BSv) * kD;
    __shared__ float s_m[kD];
    int tid = threadIdx.x;
    if (tid < kD) {
        float s = 0.f;
        #pragma unroll 8
        for (int i = 0; i < BSv; i++) s += Kt[(size_t)i*kD + tid];
        s_m[tid] = s * (1.0f/64.0f);
    }
    __syncthreads();
    float* KRo = g_KR + ((size_t)(bh*Lv + k) * BSv) * kD;
    #pragma unroll
    for (int it = 0; it < (BSv*kD)/256; it++) {
        int idx = tid + it*256;
        KRo[idx] = s_m[idx & 63];
    }
}

// ---------------- left step: per (bh, j), fused, FFMA2 ----------------
// Transposed arrays use XOR swizzle: phys(l, v) = v*32 + (l ^ (((v>>1)&15)<<1))
// measured regs=52 -> 4 CTAs. (256,5) asks for <=51 (1-reg trim, spill-free)
// -> 5 CTAs = 40 warps/SM. (The (256,6)/42-reg ask in R15 spilled and regressed.)
template<bool INIT, bool LAST>
__global__ void __launch_bounds__(256, 5) left_step_kernel(const float* __restrict__ query, int s) {
    __shared__ float s_left[Lv*Lv];
    __shared__ float s_qT[kD*Lv];
    __shared__ float s_krT[kD*Lv];
    __shared__ float s_q[Lv*kD];
    __shared__ float s_r2c[Lv];

    int bh = blockIdx.x / BSv;
    int j  = blockIdx.x % BSv;
    int h  = bh % kH;
    int tid = threadIdx.x;
    int tx = tid & 15;        // k-tile index
    int ty = tid >> 4;        // l-tile index
    int l0 = ty*2, k0 = tx*2;

    const size_t lp_base = ((size_t)(bh*BSv + j)) * (Lv*Lv);

    // prefetch lp early (hide latency behind fill + GEMM)
    float2 lpre[2];
    if (!INIT) {
        #pragma unroll
        for (int r = 0; r < 2; r++)
            lpre[r] = *(const float2*)&g_lp[lp_base + (size_t)(l0+r)*Lv + k0];
    }
    // hoisted strided r2 gather (previously issued right before the barrier -> exposed)
    float r2v = 0.f;
    if (!INIT && tid < Lv) r2v = g_r2[(bh*Lv + tid)*BSv + j];

    // load Q (scaled) and KR; build row-major s_q and swizzled transposes
    float qsc = g_asc[h];
    const float* KRb = g_KR + (size_t)bh*Lv*BSv*kD;
    #pragma unroll
    for (int it = 0; it < 2; it++) {
        int idx = tid + it*256;            // 0..511 float4s
        int row = idx >> 4;                // l  0..31
        int m   = idx & 15;
        int vq  = m*4;
        size_t goff = ((size_t)bh*kS + (size_t)row*BSv + j)*kD + vq;
        float4 q4 = *(const float4*)&query[goff];
        q4.x *= qsc; q4.y *= qsc; q4.z *= qsc; q4.w *= qsc;
        *(float4*)&s_q[row*kD + vq] = q4;
        float4 kr4 = *(const float4*)&KRb[((size_t)row*BSv + j)*kD + vq];
        float qv[4] = {q4.x,q4.y,q4.z,q4.w};
        float kv[4] = {kr4.x,kr4.y,kr4.z,kr4.w};
        #pragma unroll
        for (int t = 0; t < 4; t++) {
            int v  = vq + t;
            int sl = row ^ (((v>>1)&15)<<1);
            s_qT [v*Lv + sl] = qv[t];
            s_krT[v*Lv + sl] = kv[t];
        }
    }
    if (!INIT && tid < Lv) s_r2c[tid] = r2v;
    __syncthreads();

    // t2l[l][k] in registers: rows l0,l0+1 ; k-pair k0,k0+1 (packed f32x2)
    ull accA = 0ull, accB = 0ull;
    #pragma unroll
    for (int v = 0; v < kD; v++) {
        int X = ((v>>1)&15)<<1;
        float2 a = *(const float2*)&s_qT[v*Lv + (l0^X)];
        ull b = *(const ull*)&s_krT[v*Lv + (k0^X)];
        fma2(accA, pdup(a.x), b);
        fma2(accB, pdup(a.y), b);
    }
    float2 t2l0 = up2(accA), t2l1 = up2(accB);

    // fused: normalize lp row, dl, project, update; store left (pre-update)
    float eta = g_eta[h*(2*NSTEPS) + s];
    float r2c0 = INIT ? 0.015625f : s_r2c[k0];
    float r2c1 = INIT ? 0.015625f : s_r2c[k0+1];
    #pragma unroll
    for (int r = 0; r < 2; r++) {
        int lr = l0 + r;
        float2 lp2 = INIT ? make_float2(0.17677669529663687f, 0.17677669529663687f)
                          : lpre[r];
        float ss = rsum16(lp2.x*lp2.x + lp2.y*lp2.y);
        float n  = sqrtf(ss);
        float sc   = n > 0.f ? 1.0f/n : 1.0f;
        float invn = n > 0.f ? 1.0f/n : 0.0f;
        float ls0 = lp2.x*sc, ls1 = lp2.y*sc;
        float le0 = ls0*ls0,  le1 = ls1*ls1;
        *(float2*)&s_left[lr*Lv + k0] = make_float2(le0, le1);
        float t0 = (r==0) ? t2l0.x : t2l1.x;
        float t1 = (r==0) ? t2l0.y : t2l1.y;
        float dl0 = (r2c0*le0 - t0) * 2.f * ls0;
        float dl1 = (r2c1*le1 - t1) * 2.f * ls1;
        float dot = rsum16(ls0*dl0 + ls1*dl1);
        dl0 = (dl0 - ls0*dot) * invn;
        dl1 = (dl1 - ls1*dot) * invn;
        float np0 = lp2.x - eta*dl0;
        float np1 = lp2.y - eta*dl1;
        if (!LAST) {
            *(float2*)&g_lp[lp_base + (size_t)lr*Lv + k0] = make_float2(np0, np1);
        } else {
            float ss2 = rsum16(np0*np0 + np1*np1);
            float n2  = sqrtf(ss2);
            float sc2 = n2 > 0.f ? 1.0f/n2 : 1.0f;
            float f0 = np0*sc2, f1 = np1*sc2;
            *(float2*)&g_leftF[lp_base + (size_t)lr*Lv + k0] = make_float2(f0*f0, f1*f1);
        }
    }
    __syncthreads();

    // l2[k] = sum_l left^2
    if (tid < Lv) {
        float acc = 0.f;
        #pragma unroll
        for (int l = 0; l < Lv; l++) { float vv = s_left[l*Lv + tid]; acc += vv*vv; }
        g_l2[(size_t)(bh*BSv + j)*Lv + tid] = acc;
    }

    // LQ[kk][v] = sum_l left[l][kk]*q[l][v] : kk pair ty*2, v0=tx*4, FFMA2
    {
        int kk0 = ty*2, v0 = tx*4;
        ull a0p0=0ull, a0p1=0ull, a1p0=0ull, a1p1=0ull;
        #pragma unroll
        for (int l = 0; l < Lv; l++) {
            float2 a = *(const float2*)&s_left[l*Lv + kk0];
            ulonglong2 b = *(const ulonglong2*)&s_q[l*kD + v0];
            ull ad0 = pdup(a.x), ad1 = pdup(a.y);
            fma2(a0p0, ad0, b.x); fma2(a0p1, ad0, b.y);
            fma2(a1p0, ad1, b.x); fma2(a1p1, ad1, b.y);
        }
        float* LQo = g_LQ + ((size_t)(bh*BSv + j)) * Lv * kD;
        float2 r00 = up2(a0p0), r01 = up2(a0p1), r10 = up2(a1p0), r11 = up2(a1p1);
        *(float4*)&LQo[(size_t)kk0*kD + v0]     = make_float4(r00.x,r00.y,r01.x,r01.y);
        *(float4*)&LQo[(size_t)(kk0+1)*kD + v0] = make_float4(r10.x,r10.y,r11.x,r11.y);
    }
}

// ---------------- right step: per (bh, k), fused, FFMA2 ----------------
// Transposed arrays use XOR swizzle: phys(i, v) = v*64 + (i ^ (((v>>2)&7)<<2))
// smem 33KB (rp staging removed), __launch_bounds__(256,5) -> regs=48, 5 CTAs/SM.
#define SMEM_RT_FLOATS (4096*2 + 64)

template<bool INIT, int MODE>  // MODE 0 = update rp + next KR/r2 ; 1 = last step: Y from V
__global__ void __launch_bounds__(256, 5) right_step_kernel(const float* __restrict__ key,
                                                            const float* __restrict__ val,
                                                            int s) {
    extern __shared__ float sm[];
    float* s_KT  = sm;            // swizzled transposed K [v][i']; after GEMM1: swizzled rightT [i][j']
    float* s_LQT = sm + 4096;     // swizzled transposed LQ [v][j']; after GEMM1: row-major Km (cp.async)
    float* s_l2  = sm + 8192;     // 64

    int bh = blockIdx.x / Lv;
    int k  = blockIdx.x % Lv;
    int h  = bh % kH;
    int tid = threadIdx.x;
    int tx = tid & 15;
    int ty = tid >> 4;
    int j0 = ty*4, i0 = tx*4;

    const size_t rp_base = ((size_t)(bh*Lv + k)) * (BSv*BSv);
    const float* Kt  = key + ((size_t)bh*kS + (size_t)k*BSv) * kD;
    const float* Vt  = val + ((size_t)bh*kS + (size_t)k*BSv) * kD;
    const float* LQb = g_LQ + (size_t)bh*BSv*Lv*kD + (size_t)k*kD;

    // load K and LQ, transposed+swizzled
    #pragma unroll
    for (int it = 0; it < 4; it++) {
        int idx = tid + it*256;        // 0..1023 float4s
        int row = idx >> 4;            // i or j: 0..63
        int m   = idx & 15;
        int vq  = m*4;
        int sr  = row ^ ((m & 7) << 2);
        float4 k4 = *(const float4*)&Kt[(size_t)row*kD + vq];
        float4 l4 = *(const float4*)&LQb[(size_t)row*(Lv*kD) + vq];
        s_KT [(vq+0)*BSv + sr] = k4.x; s_KT [(vq+1)*BSv + sr] = k4.y;
        s_KT [(vq+2)*BSv + sr] = k4.z; s_KT [(vq+3)*BSv + sr] = k4.w;
        s_LQT[(vq+0)*BSv + sr] = l4.x; s_LQT[(vq+1)*BSv + sr] = l4.y;
        s_LQT[(vq+2)*BSv + sr] = l4.z; s_LQT[(vq+3)*BSv + sr] = l4.w;
    }
    if (tid < BSv) s_l2[tid] = g_l2[(size_t)(bh*BSv + tid)*Lv + k];
    __syncthreads();

    // GEMM1: t2r[j][i] = sum_v LQ[j][v]*K[i][v]  (registers, 4x4 tiles, packed f32x2)
    ull acc[4][2] = {};
    #pragma unroll
    for (int v = 0; v < kD; v++) {
        int xo = ((v>>2)&7)<<2;
        float4 a4 = *(const float4*)&s_LQT[v*BSv + (j0^xo)];
        ulonglong2 b2 = *(const ulonglong2*)&s_KT[v*BSv + (i0^xo)];
        ull a0 = pdup(a4.x), a1 = pdup(a4.y), a2 = pdup(a4.z), a3 = pdup(a4.w);
        fma2(acc[0][0], a0, b2.x); fma2(acc[0][1], a0, b2.y);
        fma2(acc[1][0], a1, b2.x); fma2(acc[1][1], a1, b2.y);
        fma2(acc[2][0], a2, b2.x); fma2(acc[2][1], a2, b2.y);
        fma2(acc[3][0], a3, b2.x); fma2(acc[3][1], a3, b2.y);
    }
    __syncthreads();   // everyone done reading s_KT / s_LQT

    // Km (K for MODE0, V for MODE1) -> s_LQT region, overlapped with dr phase
    {
        uint32_t sdst = (uint32_t)__cvta_generic_to_shared(s_LQT);
        const float4* Gp = (const float4*)(MODE == 0 ? Kt : Vt);
        #pragma unroll
        for (int it = 0; it < 4; it++) {
            int idx = tid + it*256;          // 0..1023 float4s
            cp_async16(sdst + (uint32_t)idx*16, Gp + idx);
        }
        cp_async_commit();
    }

    // fused dr: normalize rp row (gmem, in-loop — measured equal to smem staging),
    // grad, project, update, renormalize; rightT -> s_KT
    float eta = g_eta[h*(2*NSTEPS) + NSTEPS + s];
    int sxo = (tx & 7) << 2;   // ((i0+c)>>2 & 7)<<2, constant over c
    #pragma unroll
    for (int r = 0; r < 4; r++) {
        int jr = j0 + r;
        float4 rp4 = INIT ? make_float4(0.125f, 0.125f, 0.125f, 0.125f)
                          : *(const float4*)&g_rp[rp_base + (size_t)jr*BSv + i0];
        float ss = rsum16(rp4.x*rp4.x + rp4.y*rp4.y + rp4.z*rp4.z + rp4.w*rp4.w);
        float n  = sqrtf(ss);
        float sc   = n > 0.f ? 1.0f/n : 1.0f;
        float invn = n > 0.f ? 1.0f/n : 0.0f;
        float rs0 = rp4.x*sc, rs1 = rp4.y*sc, rs2 = rp4.z*sc, rs3 = rp4.w*sc;
        float l2v = s_l2[jr];
        float2 t01 = up2(acc[r][0]);
        float2 t23 = up2(acc[r][1]);
        float dr0 = (l2v*rs0*rs0 - t01.x) * 2.f * rs0;
        float dr1 = (l2v*rs1*rs1 - t01.y) * 2.f * rs1;
        float dr2 = (l2v*rs2*rs2 - t23.x) * 2.f * rs2;
        float dr3 = (l2v*rs3*rs3 - t23.y) * 2.f * rs3;
        float dot = rsum16(rs0*dr0 + rs1*dr1 + rs2*dr2 + rs3*dr3);
        dr0 = (dr0 - rs0*dot) * invn;
        dr1 = (dr1 - rs1*dot) * invn;
        dr2 = (dr2 - rs2*dot) * invn;
        dr3 = (dr3 - rs3*dot) * invn;
        float np0 = rp4.x - eta*dr0;
        float np1 = rp4.y - eta*dr1;
        float np2 = rp4.z - eta*dr2;
        float np3 = rp4.w - eta*dr3;
        if (MODE == 0) {
            *(float4*)&g_rp[rp_base + (size_t)jr*BSv + i0] = make_float4(np0,np1,np2,np3);
        }
        float ss2 = rsum16(np0*np0 + np1*np1 + np2*np2 + np3*np3);
        float n2  = sqrtf(ss2);
        float sc2 = n2 > 0.f ? 1.0f/n2 : 1.0f;
        float rn0 = np0*sc2, rn1 = np1*sc2, rn2 = np2*sc2, rn3 = np3*sc2;
        float rt0 = rn0*rn0, rt1 = rn1*rn1, rt2 = rn2*rn2, rt3 = rn3*rn3;
        // rightT[i][j'] into s_KT region (swizzled on i)
        int sj = jr ^ sxo;
        s_KT[(i0+0)*BSv + sj] = rt0;
        s_KT[(i0+1)*BSv + sj] = rt1;
        s_KT[(i0+2)*BSv + sj] = rt2;
        s_KT[(i0+3)*BSv + sj] = rt3;
        if (MODE == 0) {
            float r2s = rsum16(rt0*rt0 + rt1*rt1 + rt2*rt2 + rt3*rt3);
            if (tx == 0) g_r2[(bh*Lv + k)*BSv + jr] = r2s;
        }
    }
    cp_async_wait0();   // Km complete
    __syncthreads();

    // GEMM2: OUT[j][v] = sum_i rightT[i][j] * Km[i][v]  -> g_KR (next KR, or Y)
    float* outp = g_KR + ((size_t)(bh*Lv + k) * BSv) * kD;
    {
        int v0 = tx*4;
        ull acc2[4][2] = {};
        #pragma unroll
        for (int i = 0; i < BSv; i++) {
            int xo = ((i>>2)&7)<<2;
            float4 a4 = *(const float4*)&s_KT[i*BSv + (j0^xo)];
            ulonglong2 b2 = *(const ulonglong2*)&s_LQT[i*kD + v0];
            ull a0 = pdup(a4.x), a1 = pdup(a4.y), a2 = pdup(a4.z), a3 = pdup(a4.w);
            fma2(acc2[0][0], a0, b2.x); fma2(acc2[0][1], a0, b2.y);
            fma2(acc2[1][0], a1, b2.x); fma2(acc2[1][1], a1, b2.y);
            fma2(acc2[2][0], a2, b2.x); fma2(acc2[2][1], a2, b2.y);
            fma2(acc2[3][0], a3, b2.x); fma2(acc2[3][1], a3, b2.y);
        }
        #pragma unroll
        for (int r = 0; r < 4; r++) {
            float2 o01 = up2(acc2[r][0]);
            float2 o23 = up2(acc2[r][1]);
            *(float4*)&outp[(size_t)(j0+r)*kD + v0] = make_float4(o01.x,o01.y,o23.x,o23.y);
        }
    }
}

// ---------------- final Z = left @ Y, scatter to output ----------------
__global__ void __launch_bounds__(256) zout_kernel(float* __restrict__ out) {
    __shared__ float s_left[Lv*Lv];
    __shared__ float s_y[Lv*kD];
    int bh = blockIdx.x / BSv;
    int j  = blockIdx.x % BSv;
    int tid = threadIdx.x;
    size_t lbase = ((size_t)(bh*BSv + j)) * (Lv*Lv);
    #pragma unroll
    for (int it = 0; it < 4; it++) {
        int idx = tid + it*256;
        s_left[idx] = g_leftF[lbase + idx];
    }
    const float* Yb = g_KR + (size_t)bh*Lv*BSv*kD + (size_t)j*kD;
    #pragma unroll
    for (int it = 0; it < 8; it++) {
        int idx = tid + it*256;
        int kk = idx >> 6, v = idx & 63;
        s_y[kk*kD + v] = Yb[(size_t)kk*(BSv*kD) + v];
    }
    __syncthreads();
    int tx = tid & 15, ty = tid >> 4;
    int l00 = ty*2, v0 = tx*4;
    ull a0p0=0ull, a0p1=0ull, a1p0=0ull, a1p1=0ull;
    #pragma unroll
    for (int kk = 0; kk < Lv; kk++) {
        float a0 = s_left[l00*Lv + kk];
        float a1 = s_left[(l00+1)*Lv + kk];
        ulonglong2 b = *(const ulonglong2*)&s_y[kk*kD + v0];
        ull ad0 = pdup(a0), ad1 = pdup(a1);
        fma2(a0p0, ad0, b.x); fma2(a0p1, ad0, b.y);
        fma2(a1p0, ad1, b.x); fma2(a1p1, ad1, b.y);
    }
    float2 r00 = up2(a0p0), r01 = up2(a0p1), r10 = up2(a1p0), r11 = up2(a1p1);
    *(float4*)&out[((size_t)bh*kS + (size_t)l00*BSv + j)*kD + v0] =
        make_float4(r00.x,r00.y,r01.x,r01.y);
    *(float4*)&out[((size_t)bh*kS + (size_t)(l00+1)*BSv + j)*kD + v0] =
        make_float4(r10.x,r10.y,r11.x,r11.y);
}

// ---------------- launch ----------------
extern "C" void kernel_launch(void* const* d_in, const int* in_sizes, int n_in,
                              void* d_out, int out_size) {
    (void)in_sizes; (void)n_in; (void)out_size;
    const float* q      = (const float*)d_in[0];
    const float* key    = (const float*)d_in[1];
    const float* val    = (const float*)d_in[2];
    const float* ascale = (const float*)d_in[3];
    const float* ssz    = (const float*)d_in[4];
    float* out = (float*)d_out;

    const size_t SMEM_R = (size_t)SMEM_RT_FLOATS * sizeof(float);
    cudaFuncSetAttribute(right_step_kernel<true,0>,  cudaFuncAttributeMaxDynamicSharedMemorySize, (int)SMEM_R);
    cudaFuncSetAttribute(right_step_kernel<false,0>, cudaFuncAttributeMaxDynamicSharedMemorySize, (int)SMEM_R);
    cudaFuncSetAttribute(right_step_kernel<false,1>, cudaFuncAttributeMaxDynamicSharedMemorySize, (int)SMEM_R);

    prep_kernel<<<1, 128>>>(ascale, ssz);
    init_kr_kernel<<<BH*Lv, 256>>>(key);

    // s = 0 (INIT: lp/rp are exact constants)
    left_step_kernel<true,false><<<BH*BSv, 256>>>(q, 0);
    right_step_kernel<true,0><<<BH*Lv, 256, SMEM_R>>>(key, val, 0);
    // s = 1..2
    for (int s = 1; s < NSTEPS-1; s++) {
        left_step_kernel<false,false><<<BH*BSv, 256>>>(q, s);
        right_step_kernel<false,0><<<BH*Lv, 256, SMEM_R>>>(key, val, s);
    }
    // s = 3 (LAST: left -> leftF, right -> Y from V)
    left_step_kernel<false,true><<<BH*BSv, 256>>>(q, NSTEPS-1);
    right_step_kernel<false,1><<<BH*Lv, 256, SMEM_R>>>(key, val, NSTEPS-1);

    zout_kernel<<<BH*BSv, 256>>>(out);
}